// round 6
// baseline (speedup 1.0000x reference)
#include <cuda_runtime.h>
#include <math.h>

#define BB 12
#define CC 64
#define KK 32
#define VV 32768
#define MID 32
#define RED 16

#define OUT_RF 0
#define OUT_SP (BB*KK*CC)                 /* 24576  */
#define OUT_ZO (OUT_SP + BB*VV)           /* 417792 */
#define OUT_LOSS (OUT_ZO + BB*CC*VV)      /* 25583616 */

// ------------------------ device scratch (static, no allocs) ------------------
__device__ unsigned g_maskbits[VV];
__device__ float g_msum[KK];
__device__ float g_A2[BB*CC*27*KK];       // [m=b*64+o][off*32+k]
__device__ float g_Wk[BB*KK];
__device__ float g_mod[BB*KK*CC];         // [b][k][c]
__device__ float g_dot[BB*MID], g_n1[BB*MID], g_n2[BB*MID];
__device__ float g_reg;

// ------------------------ init accumulators (every launch) --------------------
__global__ void k_init() {
    int t = threadIdx.x;
    if (t < BB*MID) { g_dot[t] = 0.f; g_n1[t] = 0.f; g_n2[t] = 0.f; }
    if (t == 0) g_reg = 0.f;
}

// ------------------------ mask bit-packing + sums -----------------------------
__global__ void k_maskbits(const float* __restrict__ masks) {
    int v = blockIdx.x * 256 + threadIdx.x;
    unsigned w = 0;
#pragma unroll
    for (int k = 0; k < KK; k++)
        if (masks[k*VV + v] > 0.5f) w |= (1u << k);
    g_maskbits[v] = w;
}

__global__ void k_msum(const float* __restrict__ masks) {
    int k = blockIdx.x;
    float s = 0.f;
    for (int v = threadIdx.x; v < VV; v += 256) s += masks[k*VV + v];
    __shared__ float sm[8];
#pragma unroll
    for (int o = 16; o; o >>= 1) s += __shfl_xor_sync(0xffffffffu, s, o);
    if ((threadIdx.x & 31) == 0) sm[threadIdx.x >> 5] = s;
    __syncthreads();
    if (threadIdx.x == 0) {
        float t = 0.f;
        for (int i = 0; i < 8; i++) t += sm[i];
        g_msum[k] = t;
    }
}

// ------------------------ rf[b,k,c] -------------------------------------------
__global__ __launch_bounds__(256) void k_rf(const float* __restrict__ Z,
                                            float* __restrict__ out) {
    int b = blockIdx.x / CC, c = blockIdx.x % CC;
    const float* z = Z + (size_t)blockIdx.x * VV;
    float acc[KK];
#pragma unroll
    for (int k = 0; k < KK; k++) acc[k] = 0.f;
    for (int v = threadIdx.x; v < VV; v += 256) {
        float zv = z[v];
        unsigned bits = g_maskbits[v];
#pragma unroll
        for (int k = 0; k < KK; k++)
            acc[k] += (bits & (1u << k)) ? zv : 0.f;
    }
    __shared__ float sm[8*KK];
    int lane = threadIdx.x & 31, warp = threadIdx.x >> 5;
#pragma unroll
    for (int k = 0; k < KK; k++) {
        float v = acc[k];
#pragma unroll
        for (int o = 16; o; o >>= 1) v += __shfl_xor_sync(0xffffffffu, v, o);
        if (lane == k) sm[warp*KK + k] = v;
    }
    __syncthreads();
    if (threadIdx.x < KK) {
        int k = threadIdx.x;
        float t = 0.f;
#pragma unroll
        for (int w = 0; w < 8; w++) t += sm[w*KK + k];
        out[OUT_RF + (b*KK + k)*CC + c] = t / (g_msum[k] + 1e-6f);
    }
}

// ------------------------ MMD / reg / Wk / mod (tiny, 1 block) ----------------
__global__ __launch_bounds__(384) void k_stats(const float* __restrict__ outbuf,
        const int* __restrict__ labels, const float* __restrict__ ages,
        const float* __restrict__ pw,
        const float* __restrict__ mw1, const float* __restrict__ mb1,
        const float* __restrict__ mw2, const float* __restrict__ mb2) {
    __shared__ float x2_s[KK*BB];
    __shared__ float d2_s[KK*BB*BB];
    __shared__ float dk_s[4*KK];
    __shared__ float Dm_s[KK], nm_s[KK], base_s[KK], af_s[BB];
    __shared__ int   labi[BB];
    __shared__ float cnt[3];
    const float* rf = outbuf + OUT_RF;
    int t = threadIdx.x;

    if (t < BB) labi[t] = labels[t];
    if (t < 3)  cnt[t] = 0.f;
    __syncthreads();
    if (t == 0) for (int i = 0; i < BB; i++) cnt[labi[i]] += 1.f;

    // x2[b,k]
    if (t < BB*KK) {
        int b = t / KK, k = t % KK;
        const float* r = rf + (b*KK + k)*CC;
        float s = 0.f;
        for (int c = 0; c < CC; c++) s += r[c]*r[c];
        x2_s[k*BB + b] = s;
    }
    __syncthreads();
    // d2[k,i,j]
    for (int e = t; e < KK*BB*BB; e += 384) {
        int k = e / (BB*BB), r = e % (BB*BB), i = r / BB, j = r % BB;
        const float* ri = rf + (i*KK + k)*CC;
        const float* rj = rf + (j*KK + k)*CC;
        float s = 0.f;
        for (int c = 0; c < CC; c++) s += ri[c]*rj[c];
        d2_s[e] = fmaxf(x2_s[k*BB + i] + x2_s[k*BB + j] - 2.f*s, 0.f);
    }
    __syncthreads();
    // MMD per (sigma, k)
    if (t < 4*KK) {
        int si = t / KK, k = t % KK;
        const float sig[4] = {0.1f, 0.5f, 1.0f, 2.0f};
        float inv = 1.f / (2.f * sig[si]*sig[si]);
        float S[9]; float dd[3];
        for (int i = 0; i < 9; i++) S[i] = 0.f;
        dd[0] = dd[1] = dd[2] = 0.f;
        for (int i = 0; i < BB; i++) {
            int la = labi[i];
            for (int j = 0; j < BB; j++) {
                float kv = expf(-d2_s[k*BB*BB + i*BB + j] * inv);
                S[la*3 + labi[j]] += kv;
                if (i == j) dd[la] += kv;
            }
        }
        const int pa[3] = {2, 1, 2}, pb[3] = {0, 0, 1};
        float psum = 0.f;
        for (int p = 0; p < 3; p++) {
            float m = cnt[pa[p]], n = cnt[pb[p]];
            float t1 = (S[pa[p]*3 + pa[p]] - dd[pa[p]]) / (m*(m - 1.f));
            float t2 = (S[pb[p]*3 + pb[p]] - dd[pb[p]]) / (n*(n - 1.f));
            float t3 = S[pa[p]*3 + pb[p]] * (-2.f / (m*n));
            psum += t1 + t2 + t3;
        }
        dk_s[si*KK + k] = psum;
    }
    __syncthreads();
    if (t < KK)
        Dm_s[t] = 0.25f*(dk_s[t] + dk_s[KK + t] + dk_s[2*KK + t] + dk_s[3*KK + t]);
    __syncthreads();
    if (t == 0) {
        float mx = Dm_s[0];
        for (int k = 1; k < KK; k++) mx = fmaxf(mx, Dm_s[k]);
        mx = fmaxf(mx, 1e-6f);
        for (int k = 0; k < KK; k++) nm_s[k] = fmaxf(Dm_s[k]/mx, 0.f);
        float mp = -1e30f, mq = -1e30f;
        for (int k = 0; k < KK; k++) { mp = fmaxf(mp, pw[k]); mq = fmaxf(mq, nm_s[k]); }
        float sp = 0.f, sq = 0.f;
        for (int k = 0; k < KK; k++) { sp += expf(pw[k]-mp); sq += expf(nm_s[k]-mq); }
        float lsp = mp + logf(sp), lsq = mq + logf(sq);
        float reg = 0.f;
        for (int k = 0; k < KK; k++) {
            float lpk = pw[k] - lsp, lqk = nm_s[k] - lsq;
            float p = expf(lpk), q = expf(lqk);
            reg += 0.5f*q*(lqk - lpk) + 0.5f*p*(lpk - lqk);
        }
        g_reg = reg / (float)KK;
    }
    __syncthreads();
    if (t < KK) base_s[t] = 0.7f*pw[t] + 0.3f*nm_s[t];
    if (t < BB) {
        float x = 0.1f*(ages[t] - 50.f);
        af_s[t] = 1.f + fmaxf(x, 0.f) + log1pf(expf(-fabsf(x)));
    }
    __syncthreads();
    // Wk: warp b handles its 32 regions
    {
        int b = t >> 5, lane = t & 31;
        float v = fminf(fmaxf(base_s[lane]*af_s[b], 0.f), 2.f);
        float m = v;
#pragma unroll
        for (int o = 16; o; o >>= 1) m = fmaxf(m, __shfl_xor_sync(0xffffffffu, m, o));
        float e = expf(v - m);
        float s = e;
#pragma unroll
        for (int o = 16; o; o >>= 1) s += __shfl_xor_sync(0xffffffffu, s, o);
        g_Wk[b*KK + lane] = e / s;
    }
    // mod[b,k,c]: thread per (b,k)
    {
        int b = t / KK, k = t % KK;
        float r[CC];
        const float* rr = rf + (b*KK + k)*CC;
        for (int c = 0; c < CC; c++) r[c] = rr[c];
        float h[RED];
#pragma unroll
        for (int q = 0; q < RED; q++) {
            float a = mb1[q];
            for (int c = 0; c < CC; c++) a += r[c]*mw1[q*CC + c];
            h[q] = fmaxf(a, 0.f);
        }
        for (int c = 0; c < CC; c++) {
            float a = mb2[c];
#pragma unroll
            for (int q = 0; q < RED; q++) a += h[q]*mw2[c*RED + q];
            g_mod[(b*KK + k)*CC + c] = fmaxf(a, 0.f) + log1pf(expf(-fabsf(a)));
        }
    }
}

// ------------------------ A2[b,o,off,k] ---------------------------------------
__global__ __launch_bounds__(256) void k_A2(const float* __restrict__ outbuf,
                                            const float* __restrict__ rw) {
    int m = blockIdx.x;                 // b*64 + o
    int b = m / CC, o = m % CC;
    __shared__ float rf_s[KK*CC];
    __shared__ float rw_s[CC*27];
    const float* rf = outbuf + OUT_RF + b*KK*CC;
    for (int i = threadIdx.x; i < KK*CC; i += 256) rf_s[i] = rf[i];
    for (int i = threadIdx.x; i < CC*27; i += 256) rw_s[i] = rw[o*CC*27 + i];
    __syncthreads();
    for (int t = threadIdx.x; t < 27*KK; t += 256) {
        int off = t / KK, k = t % KK;
        float a = 0.f;
        for (int c = 0; c < CC; c++) a += rf_s[k*CC + c] * rw_s[c*27 + off];
        g_A2[(size_t)m*(27*KK) + off*KK + k] = a;
    }
}

// ------------------------ Z_clean + ortho stats -------------------------------
__global__ __launch_bounds__(256) void k_zclean(const float* __restrict__ Z,
        const float* __restrict__ sw, const float* __restrict__ nw,
        const float* __restrict__ uw, float* __restrict__ out) {
    int b = blockIdx.y;
    int v = blockIdx.x*256 + threadIdx.x;
    __shared__ float sw_s[MID*CC], nw_s[MID*CC], uw_s[CC*MID];
    __shared__ float red[3*MID];
    for (int i = threadIdx.x; i < MID*CC; i += 256) {
        sw_s[i] = sw[i]; nw_s[i] = nw[i]; uw_s[i] = uw[i];
    }
    if (threadIdx.x < 3*MID) red[threadIdx.x] = 0.f;
    __syncthreads();
    float cs[MID], cn[MID];
#pragma unroll
    for (int o = 0; o < MID; o++) { cs[o] = 0.f; cn[o] = 0.f; }
    const float* zb = Z + (size_t)b*CC*VV;
    for (int c = 0; c < CC; c++) {
        float z = zb[(size_t)c*VV + v];
#pragma unroll
        for (int o = 0; o < MID; o++) {
            cs[o] += sw_s[o*CC + c]*z;
            cn[o] += nw_s[o*CC + c]*z;
        }
    }
    int lane = threadIdx.x & 31;
#pragma unroll
    for (int o = 0; o < MID; o++) {
        float d = cs[o]*cn[o], a = cs[o]*cs[o], e = cn[o]*cn[o];
#pragma unroll
        for (int s = 16; s; s >>= 1) {
            d += __shfl_xor_sync(0xffffffffu, d, s);
            a += __shfl_xor_sync(0xffffffffu, a, s);
            e += __shfl_xor_sync(0xffffffffu, e, s);
        }
        if (lane == 0) {
            atomicAdd(&red[o], d);
            atomicAdd(&red[MID + o], a);
            atomicAdd(&red[2*MID + o], e);
        }
    }
    __syncthreads();
    if (threadIdx.x < MID) {
        atomicAdd(&g_dot[b*MID + threadIdx.x], red[threadIdx.x]);
        atomicAdd(&g_n1[b*MID + threadIdx.x], red[MID + threadIdx.x]);
        atomicAdd(&g_n2[b*MID + threadIdx.x], red[2*MID + threadIdx.x]);
    }
    float* zo = out + OUT_ZO + (size_t)b*CC*VV + v;
#pragma unroll
    for (int half = 0; half < 2; half++) {
        float zc[32];
#pragma unroll
        for (int j = 0; j < 32; j++) zc[j] = 0.f;
#pragma unroll
        for (int o = 0; o < MID; o++) {
            float co = cs[o];
#pragma unroll
            for (int j = 0; j < 32; j++) zc[j] += uw_s[(half*32 + j)*MID + o]*co;
        }
#pragma unroll
        for (int j = 0; j < 32; j++) zo[(size_t)(half*32 + j)*VV] = zc[j];
    }
}

// ------------------------ spatial[b,v] ----------------------------------------
__global__ __launch_bounds__(256) void k_spatial(float* __restrict__ out) {
    int b = blockIdx.y;
    int v = blockIdx.x*256 + threadIdx.x;
    __shared__ float wk[KK];
    if (threadIdx.x < KK) wk[threadIdx.x] = g_Wk[b*KK + threadIdx.x];
    __syncthreads();
    unsigned bits = g_maskbits[v];
    float s = 0.f;
#pragma unroll
    for (int k = 0; k < KK; k++) s += (bits & (1u << k)) ? wk[k] : 0.f;
    out[OUT_SP + b*VV + v] = s;
}

// ------------------------ conv-as-GEMM + fused epilogue -----------------------
// Zrec[b,o,v] = sum_{off,k} A2[b,o,off,k] * mask[k, v + delta(off)]
// out[b,o,v] += 0.1 * Zrec * (sum_k mod[b,k,o]*mask[k,v]) * spatial[b,v]
__global__ __launch_bounds__(256) void k_conv(float* __restrict__ out) {
    int b = blockIdx.y;
    int n0 = blockIdx.x * 128;
    int tid = threadIdx.x;
    int ty = tid >> 5;     // 0..7  -> 8 channels each
    int tx = tid & 31;     // 0..31 -> 4 voxels each
    __shared__ float A_s[KK][CC];
    __shared__ float S_s[KK][128];
    __shared__ float mod_s[KK][CC];
    for (int i = tid; i < KK*CC; i += 256)
        mod_s[i >> 6][i & 63] = g_mod[b*KK*CC + i];
    float acc[8][4];
#pragma unroll
    for (int i = 0; i < 8; i++)
#pragma unroll
        for (int j = 0; j < 4; j++) acc[i][j] = 0.f;

    int d0 = n0 >> 10;
    for (int off = 0; off < 27; off++) {
        int dz = off/9 - 1, dy = (off/3)%3 - 1, dx = off%3 - 1;
        __syncthreads();
        for (int i = tid; i < KK*CC; i += 256) {
            int m = i >> 5, kk = i & 31;
            A_s[kk][m] = g_A2[(size_t)(b*CC + m)*(27*KK) + off*KK + kk];
        }
        {
            int vv = tid & 127, kh = tid >> 7;
            int vg = n0 + vv;
            int d = d0 + dz;
            int h = ((vg >> 5) & 31) + dy;
            int w = (vg & 31) + dx;
            unsigned word = 0;
            if ((unsigned)d < 32u && (unsigned)h < 32u && (unsigned)w < 32u)
                word = g_maskbits[(d << 10) + (h << 5) + w];
#pragma unroll
            for (int k = 0; k < 16; k++) {
                int kk = kh*16 + k;
                S_s[kk][vv] = (word & (1u << kk)) ? 1.f : 0.f;
            }
        }
        __syncthreads();
#pragma unroll
        for (int kk = 0; kk < KK; kk++) {
            float a[8];
#pragma unroll
            for (int i = 0; i < 8; i++) a[i] = A_s[kk][ty*8 + i];
            float4 sv = *(const float4*)&S_s[kk][tx*4];
#pragma unroll
            for (int i = 0; i < 8; i++) {
                acc[i][0] += a[i]*sv.x;
                acc[i][1] += a[i]*sv.y;
                acc[i][2] += a[i]*sv.z;
                acc[i][3] += a[i]*sv.w;
            }
        }
    }
    // epilogue: scale acc in place
    int vbase = n0 + tx*4;
#pragma unroll
    for (int j = 0; j < 4; j++) {
        int v = vbase + j;
        unsigned bits = g_maskbits[v];
        float m8[8];
#pragma unroll
        for (int i = 0; i < 8; i++) m8[i] = 0.f;
#pragma unroll
        for (int k = 0; k < KK; k++) {
            if (bits & (1u << k)) {
#pragma unroll
                for (int i = 0; i < 8; i++) m8[i] += mod_s[k][ty*8 + i];
            }
        }
        float sp = out[OUT_SP + b*VV + v];
#pragma unroll
        for (int i = 0; i < 8; i++) acc[i][j] *= 0.1f*m8[i]*sp;
    }
#pragma unroll
    for (int i = 0; i < 8; i++) {
        size_t addr = (size_t)OUT_ZO + ((size_t)(b*CC + ty*8 + i))*VV + vbase;
        float4 zc = *(float4*)(out + addr);
        zc.x += acc[i][0]; zc.y += acc[i][1];
        zc.z += acc[i][2]; zc.w += acc[i][3];
        *(float4*)(out + addr) = zc;
    }
}

// ------------------------ final scalar ----------------------------------------
__global__ void k_final(float* __restrict__ out) {
    int t = threadIdx.x;   // 384
    __shared__ float red[384];
    float n1 = sqrtf(g_n1[t]), n2 = sqrtf(g_n2[t]);
    float c = g_dot[t] / (fmaxf(n1, 1e-8f)*fmaxf(n2, 1e-8f));
    red[t] = fabsf(c);
    __syncthreads();
    if (t == 0) {
        float s = 0.f;
        for (int i = 0; i < 384; i++) s += red[i];
        out[OUT_LOSS] = g_reg + s/384.f;
    }
}

// ------------------------ launch ----------------------------------------------
extern "C" void kernel_launch(void* const* d_in, const int* in_sizes, int n_in,
                              void* d_out, int out_size) {
    const float* Z      = (const float*)d_in[0];
    const float* masks  = (const float*)d_in[1];
    const int*   labels = (const int*)  d_in[2];
    const float* ages   = (const float*)d_in[3];
    const float* pw     = (const float*)d_in[4];
    const float* sw     = (const float*)d_in[5];
    const float* nw     = (const float*)d_in[6];
    const float* uw     = (const float*)d_in[7];
    const float* rw     = (const float*)d_in[8];
    const float* mw1    = (const float*)d_in[9];
    const float* mb1    = (const float*)d_in[10];
    const float* mw2    = (const float*)d_in[11];
    const float* mb2    = (const float*)d_in[12];
    float* out = (float*)d_out;

    k_init<<<1, 384>>>();
    k_maskbits<<<VV/256, 256>>>(masks);
    k_msum<<<KK, 256>>>(masks);
    k_rf<<<BB*CC, 256>>>(Z, out);
    k_stats<<<1, 384>>>(out, labels, ages, pw, mw1, mb1, mw2, mb2);
    k_A2<<<BB*CC, 256>>>(out, rw);
    dim3 g5(VV/256, BB);
    k_zclean<<<g5, 256>>>(Z, sw, nw, uw, out);
    k_spatial<<<g5, 256>>>(out);
    dim3 g7(VV/128, BB);
    k_conv<<<g7, 256>>>(out);
    k_final<<<1, 384>>>(out);
}

// round 10
// speedup vs baseline: 2.0129x; 2.0129x over previous
#include <cuda_runtime.h>
#include <cuda_bf16.h>
#include <math.h>

#define BB 12
#define CC 64
#define KK 32
#define VV 32768
#define MID 32
#define RED 16

#define OUT_RF 0
#define OUT_SP (BB*KK*CC)                 /* 24576  */
#define OUT_ZO (OUT_SP + BB*VV)           /* 417792 */
#define OUT_LOSS (OUT_ZO + BB*CC*VV)      /* 25583616 */

#define A2PART (BB*27*CC*KK)              /* 663552  */
#define MODPART (BB*CC*KK)                /* 24576   */

// ------------------------ device scratch (static, no allocs) ------------------
__device__ __align__(16) unsigned g_maskbits[VV];
__device__ float g_msum[KK];
__device__ __align__(16) __nv_bfloat16 g_A2h[2*A2PART];  // [part][(b*27+off)][o][k]
__device__ __align__(16) __nv_bfloat16 g_modh[2*MODPART];// [part][b][o][k]
__device__ float g_Wk[BB*KK];
__device__ float g_dot[BB*MID], g_n1[BB*MID], g_n2[BB*MID];
__device__ float g_reg;

// ------------------------ init accumulators (every launch) --------------------
__global__ void k_init() {
    int t = threadIdx.x;
    if (t < BB*MID) { g_dot[t] = 0.f; g_n1[t] = 0.f; g_n2[t] = 0.f; }
    if (t == 0) g_reg = 0.f;
}

// ------------------------ mask bit-packing + sums -----------------------------
__global__ void k_maskbits(const float* __restrict__ masks) {
    int v = blockIdx.x * 256 + threadIdx.x;
    unsigned w = 0;
#pragma unroll
    for (int k = 0; k < KK; k++)
        if (masks[k*VV + v] > 0.5f) w |= (1u << k);
    g_maskbits[v] = w;
}

__global__ void k_msum(const float* __restrict__ masks) {
    int k = blockIdx.x;
    float s = 0.f;
    for (int v = threadIdx.x; v < VV; v += 256) s += masks[k*VV + v];
    __shared__ float sm[8];
#pragma unroll
    for (int o = 16; o; o >>= 1) s += __shfl_xor_sync(0xffffffffu, s, o);
    if ((threadIdx.x & 31) == 0) sm[threadIdx.x >> 5] = s;
    __syncthreads();
    if (threadIdx.x == 0) {
        float t = 0.f;
        for (int i = 0; i < 8; i++) t += sm[i];
        g_msum[k] = t;
    }
}

// ------------------------ rf[b,k,c] -------------------------------------------
__global__ __launch_bounds__(256) void k_rf(const float* __restrict__ Z,
                                            float* __restrict__ out) {
    int b = blockIdx.x / CC, c = blockIdx.x % CC;
    const float* z = Z + (size_t)blockIdx.x * VV;
    float acc[KK];
#pragma unroll
    for (int k = 0; k < KK; k++) acc[k] = 0.f;
    for (int v = threadIdx.x*4; v < VV; v += 1024) {
        float4 zz = *(const float4*)&z[v];
        uint4 mb = *(const uint4*)&g_maskbits[v];
#pragma unroll
        for (int k = 0; k < KK; k++) {
            unsigned m = 1u << k;
            float t0 = ((mb.x & m) ? zz.x : 0.f) + ((mb.y & m) ? zz.y : 0.f);
            float t1 = ((mb.z & m) ? zz.z : 0.f) + ((mb.w & m) ? zz.w : 0.f);
            acc[k] += t0 + t1;
        }
    }
    __shared__ float sm[8*KK];
    int lane = threadIdx.x & 31, warp = threadIdx.x >> 5;
#pragma unroll
    for (int k = 0; k < KK; k++) {
        float v = acc[k];
#pragma unroll
        for (int o = 16; o; o >>= 1) v += __shfl_xor_sync(0xffffffffu, v, o);
        if (lane == k) sm[warp*KK + k] = v;
    }
    __syncthreads();
    if (threadIdx.x < KK) {
        int k = threadIdx.x;
        float t = 0.f;
#pragma unroll
        for (int w = 0; w < 8; w++) t += sm[w*KK + k];
        out[OUT_RF + (b*KK + k)*CC + c] = t / (g_msum[k] + 1e-6f);
    }
}

// ------------------------ MMD / reg / Wk / mod (tiny, 1 block) ----------------
__global__ __launch_bounds__(384) void k_stats(const float* __restrict__ outbuf,
        const int* __restrict__ labels, const float* __restrict__ ages,
        const float* __restrict__ pw,
        const float* __restrict__ mw1, const float* __restrict__ mb1,
        const float* __restrict__ mw2, const float* __restrict__ mb2) {
    __shared__ float x2_s[KK*BB];
    __shared__ float d2_s[KK*BB*BB];
    __shared__ float dk_s[4*KK];
    __shared__ float Dm_s[KK], nm_s[KK], base_s[KK], af_s[BB];
    __shared__ int   labi[BB];
    __shared__ float cnt[3];
    const float* rf = outbuf + OUT_RF;
    int t = threadIdx.x;

    if (t < BB) labi[t] = labels[t];
    if (t < 3)  cnt[t] = 0.f;
    __syncthreads();
    if (t == 0) for (int i = 0; i < BB; i++) cnt[labi[i]] += 1.f;

    // x2[b,k]
    if (t < BB*KK) {
        int b = t / KK, k = t % KK;
        const float* r = rf + (b*KK + k)*CC;
        float s = 0.f;
        for (int c = 0; c < CC; c++) s += r[c]*r[c];
        x2_s[k*BB + b] = s;
    }
    __syncthreads();
    // d2[k,i,j]
    for (int e = t; e < KK*BB*BB; e += 384) {
        int k = e / (BB*BB), r = e % (BB*BB), i = r / BB, j = r % BB;
        const float* ri = rf + (i*KK + k)*CC;
        const float* rj = rf + (j*KK + k)*CC;
        float s = 0.f;
        for (int c = 0; c < CC; c++) s += ri[c]*rj[c];
        d2_s[e] = fmaxf(x2_s[k*BB + i] + x2_s[k*BB + j] - 2.f*s, 0.f);
    }
    __syncthreads();
    // MMD per (sigma, k)
    if (t < 4*KK) {
        int si = t / KK, k = t % KK;
        const float sig[4] = {0.1f, 0.5f, 1.0f, 2.0f};
        float inv = 1.f / (2.f * sig[si]*sig[si]);
        float S[9]; float dd[3];
        for (int i = 0; i < 9; i++) S[i] = 0.f;
        dd[0] = dd[1] = dd[2] = 0.f;
        for (int i = 0; i < BB; i++) {
            int la = labi[i];
            for (int j = 0; j < BB; j++) {
                float kv = expf(-d2_s[k*BB*BB + i*BB + j] * inv);
                S[la*3 + labi[j]] += kv;
                if (i == j) dd[la] += kv;
            }
        }
        const int pa[3] = {2, 1, 2}, pb[3] = {0, 0, 1};
        float psum = 0.f;
        for (int p = 0; p < 3; p++) {
            float m = cnt[pa[p]], n = cnt[pb[p]];
            float t1 = (S[pa[p]*3 + pa[p]] - dd[pa[p]]) / (m*(m - 1.f));
            float t2 = (S[pb[p]*3 + pb[p]] - dd[pb[p]]) / (n*(n - 1.f));
            float t3 = S[pa[p]*3 + pb[p]] * (-2.f / (m*n));
            psum += t1 + t2 + t3;
        }
        dk_s[si*KK + k] = psum;
    }
    __syncthreads();
    if (t < KK)
        Dm_s[t] = 0.25f*(dk_s[t] + dk_s[KK + t] + dk_s[2*KK + t] + dk_s[3*KK + t]);
    __syncthreads();
    if (t == 0) {
        float mx = Dm_s[0];
        for (int k = 1; k < KK; k++) mx = fmaxf(mx, Dm_s[k]);
        mx = fmaxf(mx, 1e-6f);
        for (int k = 0; k < KK; k++) nm_s[k] = fmaxf(Dm_s[k]/mx, 0.f);
        float mp = -1e30f, mq = -1e30f;
        for (int k = 0; k < KK; k++) { mp = fmaxf(mp, pw[k]); mq = fmaxf(mq, nm_s[k]); }
        float sp = 0.f, sq = 0.f;
        for (int k = 0; k < KK; k++) { sp += expf(pw[k]-mp); sq += expf(nm_s[k]-mq); }
        float lsp = mp + logf(sp), lsq = mq + logf(sq);
        float reg = 0.f;
        for (int k = 0; k < KK; k++) {
            float lpk = pw[k] - lsp, lqk = nm_s[k] - lsq;
            float p = expf(lpk), q = expf(lqk);
            reg += 0.5f*q*(lqk - lpk) + 0.5f*p*(lpk - lqk);
        }
        g_reg = reg / (float)KK;
    }
    __syncthreads();
    if (t < KK) base_s[t] = 0.7f*pw[t] + 0.3f*nm_s[t];
    if (t < BB) {
        float x = 0.1f*(ages[t] - 50.f);
        af_s[t] = 1.f + fmaxf(x, 0.f) + log1pf(expf(-fabsf(x)));
    }
    __syncthreads();
    // Wk: warp b handles its 32 regions
    {
        int b = t >> 5, lane = t & 31;
        float v = fminf(fmaxf(base_s[lane]*af_s[b], 0.f), 2.f);
        float m = v;
#pragma unroll
        for (int o = 16; o; o >>= 1) m = fmaxf(m, __shfl_xor_sync(0xffffffffu, m, o));
        float e = expf(v - m);
        float s = e;
#pragma unroll
        for (int o = 16; o; o >>= 1) s += __shfl_xor_sync(0xffffffffu, s, o);
        g_Wk[b*KK + lane] = e / s;
    }
    // mod[b,k,c]: thread per (b,k) -> write split-bf16 transposed [part][b][c][k]
    {
        int b = t / KK, k = t % KK;
        float r[CC];
        const float* rr = rf + (b*KK + k)*CC;
        for (int c = 0; c < CC; c++) r[c] = rr[c];
        float h[RED];
#pragma unroll
        for (int q = 0; q < RED; q++) {
            float a = mb1[q];
            for (int c = 0; c < CC; c++) a += r[c]*mw1[q*CC + c];
            h[q] = fmaxf(a, 0.f);
        }
        for (int c = 0; c < CC; c++) {
            float a = mb2[c];
#pragma unroll
            for (int q = 0; q < RED; q++) a += h[q]*mw2[c*RED + q];
            float val = fmaxf(a, 0.f) + log1pf(expf(-fabsf(a)));
            __nv_bfloat16 hi = __float2bfloat16(val);
            __nv_bfloat16 lo = __float2bfloat16(val - __bfloat162float(hi));
            g_modh[(b*CC + c)*KK + k] = hi;
            g_modh[MODPART + (b*CC + c)*KK + k] = lo;
        }
    }
}

// ------------------------ A2[part,b,off,o,k] split-bf16 -----------------------
__global__ __launch_bounds__(256) void k_A2(const float* __restrict__ outbuf,
                                            const float* __restrict__ rw) {
    int m = blockIdx.x;                 // b*64 + o
    int b = m / CC, o = m % CC;
    __shared__ float rf_s[KK*CC];
    __shared__ float rw_s[CC*27];
    const float* rf = outbuf + OUT_RF + b*KK*CC;
    for (int i = threadIdx.x; i < KK*CC; i += 256) rf_s[i] = rf[i];
    for (int i = threadIdx.x; i < CC*27; i += 256) rw_s[i] = rw[o*CC*27 + i];
    __syncthreads();
    for (int t = threadIdx.x; t < 27*KK; t += 256) {
        int off = t / KK, k = t % KK;
        float a = 0.f;
        for (int c = 0; c < CC; c++) a += rf_s[k*CC + c] * rw_s[c*27 + off];
        __nv_bfloat16 hi = __float2bfloat16(a);
        __nv_bfloat16 lo = __float2bfloat16(a - __bfloat162float(hi));
        size_t idx = ((size_t)(b*27 + off)*CC + o)*KK + k;
        g_A2h[idx] = hi;
        g_A2h[A2PART + idx] = lo;
    }
}

// ------------------------ Z_clean + ortho stats (2 voxels/thread) -------------
__global__ __launch_bounds__(128) void k_zclean(const float* __restrict__ Z,
        const float* __restrict__ sw, const float* __restrict__ nw,
        const float* __restrict__ uw, float* __restrict__ out) {
    int b = blockIdx.y;
    int v = blockIdx.x*256 + threadIdx.x*2;
    __shared__ float sw_s[MID*CC], nw_s[MID*CC], uw_s[CC*MID];
    __shared__ float red[3*MID];
    for (int i = threadIdx.x; i < MID*CC; i += 128) {
        sw_s[i] = sw[i]; nw_s[i] = nw[i]; uw_s[i] = uw[i];
    }
    if (threadIdx.x < 3*MID) red[threadIdx.x] = 0.f;
    __syncthreads();
    float cs[2][MID], cn[2][MID];
#pragma unroll
    for (int o = 0; o < MID; o++) {
        cs[0][o] = 0.f; cs[1][o] = 0.f; cn[0][o] = 0.f; cn[1][o] = 0.f;
    }
    const float* zb = Z + (size_t)b*CC*VV;
    for (int c = 0; c < CC; c++) {
        float2 z = *(const float2*)&zb[(size_t)c*VV + v];
#pragma unroll
        for (int o = 0; o < MID; o++) {
            float ws = sw_s[o*CC + c], wn_ = nw_s[o*CC + c];
            cs[0][o] += ws*z.x;  cs[1][o] += ws*z.y;
            cn[0][o] += wn_*z.x; cn[1][o] += wn_*z.y;
        }
    }
    int lane = threadIdx.x & 31;
#pragma unroll
    for (int o = 0; o < MID; o++) {
        float d = cs[0][o]*cn[0][o] + cs[1][o]*cn[1][o];
        float a = cs[0][o]*cs[0][o] + cs[1][o]*cs[1][o];
        float e = cn[0][o]*cn[0][o] + cn[1][o]*cn[1][o];
#pragma unroll
        for (int s = 16; s; s >>= 1) {
            d += __shfl_xor_sync(0xffffffffu, d, s);
            a += __shfl_xor_sync(0xffffffffu, a, s);
            e += __shfl_xor_sync(0xffffffffu, e, s);
        }
        if (lane == 0) {
            atomicAdd(&red[o], d);
            atomicAdd(&red[MID + o], a);
            atomicAdd(&red[2*MID + o], e);
        }
    }
    __syncthreads();
    if (threadIdx.x < MID) {
        atomicAdd(&g_dot[b*MID + threadIdx.x], red[threadIdx.x]);
        atomicAdd(&g_n1[b*MID + threadIdx.x], red[MID + threadIdx.x]);
        atomicAdd(&g_n2[b*MID + threadIdx.x], red[2*MID + threadIdx.x]);
    }
    float* zo = out + OUT_ZO + (size_t)b*CC*VV + v;
#pragma unroll
    for (int half = 0; half < 2; half++) {
        float zc[2][32];
#pragma unroll
        for (int j = 0; j < 32; j++) { zc[0][j] = 0.f; zc[1][j] = 0.f; }
#pragma unroll
        for (int o = 0; o < MID; o++) {
            float c0 = cs[0][o], c1 = cs[1][o];
#pragma unroll
            for (int j = 0; j < 32; j++) {
                float u = uw_s[(half*32 + j)*MID + o];
                zc[0][j] += u*c0; zc[1][j] += u*c1;
            }
        }
#pragma unroll
        for (int j = 0; j < 32; j++)
            *(float2*)&zo[(size_t)(half*32 + j)*VV] = make_float2(zc[0][j], zc[1][j]);
    }
}

// ------------------------ spatial[b,v] ----------------------------------------
__global__ __launch_bounds__(256) void k_spatial(float* __restrict__ out) {
    int b = blockIdx.y;
    int v = blockIdx.x*256 + threadIdx.x;
    __shared__ float wk[KK];
    if (threadIdx.x < KK) wk[threadIdx.x] = g_Wk[b*KK + threadIdx.x];
    __syncthreads();
    unsigned bits = g_maskbits[v];
    float s = 0.f;
#pragma unroll
    for (int k = 0; k < KK; k++) s += (bits & (1u << k)) ? wk[k] : 0.f;
    out[OUT_SP + b*VV + v] = s;
}

// ------------------------ conv-as-GEMM via mma.sync bf16 (split hi/lo) --------
// Zrec[b,o,v] = sum_{off,k} (A2hi+A2lo)[b,off,o,k] * mask[k, v + delta(off)]
// modf[b,o,v] = sum_k (modhi+modlo)[b,o,k] * mask[k,v]   (fused at off==13)
// out[b,o,v] += 0.1 * Zrec * modf * spatial[b,v]
#define MMA16816(C, A, B0, B1) \
  asm volatile("mma.sync.aligned.m16n8k16.row.col.f32.bf16.bf16.f32 " \
    "{%0,%1,%2,%3}, {%4,%5,%6,%7}, {%8,%9}, {%0,%1,%2,%3};" \
    : "+f"(C[0]), "+f"(C[1]), "+f"(C[2]), "+f"(C[3]) \
    : "r"(A[0]), "r"(A[1]), "r"(A[2]), "r"(A[3]), "r"(B0), "r"(B1))

__global__ __launch_bounds__(256, 2) void k_conv(float* __restrict__ out) {
    int b = blockIdx.y;
    int n0 = blockIdx.x * 128;
    int tid = threadIdx.x, lane = tid & 31, warp = tid >> 5;
    int wm = (warp >> 2) * 32, wn = (warp & 3) * 32;
    int d0 = n0 >> 10, h0 = (n0 >> 5) & 31;

    __shared__ __align__(16) __nv_bfloat16 A_s[2][2][64][40];  // [buf][part]
    __shared__ __align__(16) __nv_bfloat16 M_s[2][64][40];     // [part]
    __shared__ float sp_s[128];

    {
        int row = tid >> 2, col = (tid & 3) * 8;
#pragma unroll
        for (int p = 0; p < 2; p++) {
            uint4 vm = ((const uint4*)(g_modh + (size_t)p*MODPART + b*2048))[tid];
            *(uint4*)&M_s[p][row][col] = vm;
            uint4 va = ((const uint4*)(g_A2h + (size_t)p*A2PART + (size_t)(b*27 + 0)*2048))[tid];
            *(uint4*)&A_s[0][p][row][col] = va;
        }
        if (tid < 128) sp_s[tid] = out[OUT_SP + b*VV + n0 + tid];
    }
    __syncthreads();

    float acc[2][4][4], macc[2][4][4];
#pragma unroll
    for (int i = 0; i < 2; i++)
#pragma unroll
        for (int j = 0; j < 4; j++)
#pragma unroll
            for (int r = 0; r < 4; r++) { acc[i][j][r] = 0.f; macc[i][j][r] = 0.f; }

    for (int off = 0; off < 27; off++) {
        int buf = off & 1;
        if (off < 26) {
            int row = tid >> 2, col = (tid & 3) * 8;
#pragma unroll
            for (int p = 0; p < 2; p++) {
                uint4 va = ((const uint4*)(g_A2h + (size_t)p*A2PART
                             + (size_t)(b*27 + off + 1)*2048))[tid];
                *(uint4*)&A_s[buf^1][p][row][col] = va;
            }
        }
        int dz = off/9 - 1, dy = (off%9)/3 - 1, dx = off%3 - 1;
        int dd = d0 + dz, hh = h0 + (warp & 3) + dy, ww = lane + dx;
        unsigned word = 0;
        if (((unsigned)dd < 32u) && ((unsigned)hh < 32u) && ((unsigned)ww < 32u))
            word = g_maskbits[(dd << 10) + (hh << 5) + ww];

#pragma unroll
        for (int s = 0; s < 2; s++) {
            int kcol = 2*(lane & 3) + s*16;
            int r0 = wm + (lane >> 2);
            unsigned a[2][2][4], am[2][2][4];
#pragma unroll
            for (int p = 0; p < 2; p++)
#pragma unroll
            for (int i = 0; i < 2; i++) {
                a[p][i][0] = *(const unsigned*)&A_s[buf][p][r0 + i*16][kcol];
                a[p][i][1] = *(const unsigned*)&A_s[buf][p][r0 + i*16 + 8][kcol];
                a[p][i][2] = *(const unsigned*)&A_s[buf][p][r0 + i*16][kcol + 8];
                a[p][i][3] = *(const unsigned*)&A_s[buf][p][r0 + i*16 + 8][kcol + 8];
            }
            if (off == 13) {
#pragma unroll
                for (int p = 0; p < 2; p++)
#pragma unroll
                for (int i = 0; i < 2; i++) {
                    am[p][i][0] = *(const unsigned*)&M_s[p][r0 + i*16][kcol];
                    am[p][i][1] = *(const unsigned*)&M_s[p][r0 + i*16 + 8][kcol];
                    am[p][i][2] = *(const unsigned*)&M_s[p][r0 + i*16][kcol + 8];
                    am[p][i][3] = *(const unsigned*)&M_s[p][r0 + i*16 + 8][kcol + 8];
                }
            }
#pragma unroll
            for (int j = 0; j < 4; j++) {
                unsigned wj = __shfl_sync(0xffffffffu, word, j*8 + (lane >> 2));
                unsigned t = wj >> (s*16 + 2*(lane & 3));
                unsigned b0 = (t & 1u ? 0x3F80u : 0u) | (t & 2u ? 0x3F800000u : 0u);
                unsigned t2 = t >> 8;
                unsigned b1 = (t2 & 1u ? 0x3F80u : 0u) | (t2 & 2u ? 0x3F800000u : 0u);
#pragma unroll
                for (int p = 0; p < 2; p++)
#pragma unroll
                for (int i = 0; i < 2; i++) MMA16816(acc[i][j], a[p][i], b0, b1);
                if (off == 13) {
#pragma unroll
                    for (int p = 0; p < 2; p++)
#pragma unroll
                    for (int i = 0; i < 2; i++) MMA16816(macc[i][j], am[p][i], b0, b1);
                }
            }
        }
        __syncthreads();
    }

    // epilogue: out += 0.1 * Zrec * modf * spatial
#pragma unroll
    for (int i = 0; i < 2; i++) {
#pragma unroll
        for (int j = 0; j < 4; j++) {
            int col = wn + j*8 + 2*(lane & 3);
            int r0 = wm + i*16 + (lane >> 2);
            float sp0 = 0.1f*sp_s[col], sp1 = 0.1f*sp_s[col+1];
            size_t base0 = (size_t)OUT_ZO + ((size_t)(b*CC + r0))*VV + n0 + col;
            float2 o0 = *(float2*)(out + base0);
            o0.x += acc[i][j][0]*macc[i][j][0]*sp0;
            o0.y += acc[i][j][1]*macc[i][j][1]*sp1;
            *(float2*)(out + base0) = o0;
            size_t base1 = base0 + (size_t)8*VV;
            float2 o1 = *(float2*)(out + base1);
            o1.x += acc[i][j][2]*macc[i][j][2]*sp0;
            o1.y += acc[i][j][3]*macc[i][j][3]*sp1;
            *(float2*)(out + base1) = o1;
        }
    }
}

// ------------------------ final scalar ----------------------------------------
__global__ void k_final(float* __restrict__ out) {
    int t = threadIdx.x;   // 384
    __shared__ float red[384];
    float n1 = sqrtf(g_n1[t]), n2 = sqrtf(g_n2[t]);
    float c = g_dot[t] / (fmaxf(n1, 1e-8f)*fmaxf(n2, 1e-8f));
    red[t] = fabsf(c);
    __syncthreads();
    if (t == 0) {
        float s = 0.f;
        for (int i = 0; i < 384; i++) s += red[i];
        out[OUT_LOSS] = g_reg + s/384.f;
    }
}

// ------------------------ launch ----------------------------------------------
extern "C" void kernel_launch(void* const* d_in, const int* in_sizes, int n_in,
                              void* d_out, int out_size) {
    const float* Z      = (const float*)d_in[0];
    const float* masks  = (const float*)d_in[1];
    const int*   labels = (const int*)  d_in[2];
    const float* ages   = (const float*)d_in[3];
    const float* pw     = (const float*)d_in[4];
    const float* sw     = (const float*)d_in[5];
    const float* nw     = (const float*)d_in[6];
    const float* uw     = (const float*)d_in[7];
    const float* rw     = (const float*)d_in[8];
    const float* mw1    = (const float*)d_in[9];
    const float* mb1    = (const float*)d_in[10];
    const float* mw2    = (const float*)d_in[11];
    const float* mb2    = (const float*)d_in[12];
    float* out = (float*)d_out;

    k_init<<<1, 384>>>();
    k_maskbits<<<VV/256, 256>>>(masks);
    k_msum<<<KK, 256>>>(masks);
    k_rf<<<BB*CC, 256>>>(Z, out);
    k_stats<<<1, 384>>>(out, labels, ages, pw, mw1, mb1, mw2, mb2);
    k_A2<<<BB*CC, 256>>>(out, rw);
    dim3 gz(VV/256, BB);
    k_zclean<<<gz, 128>>>(Z, sw, nw, uw, out);
    dim3 gs(VV/256, BB);
    k_spatial<<<gs, 256>>>(out);
    dim3 gc(VV/128, BB);
    k_conv<<<gc, 256>>>(out);
    k_final<<<1, 384>>>(out);
}

// round 11
// speedup vs baseline: 2.1176x; 1.0520x over previous
#include <cuda_runtime.h>
#include <cuda_bf16.h>
#include <math.h>

#define BB 12
#define CC 64
#define KK 32
#define VV 32768
#define MID 32
#define RED 16

#define OUT_RF 0
#define OUT_SP (BB*KK*CC)                 /* 24576  */
#define OUT_ZO (OUT_SP + BB*VV)           /* 417792 */
#define OUT_LOSS (OUT_ZO + BB*CC*VV)      /* 25583616 */

#define A2PART (BB*27*CC*KK)              /* 663552  */
#define MODPART (BB*CC*KK)                /* 24576   */

// ------------------------ device scratch (static, no allocs) ------------------
__device__ __align__(16) unsigned g_maskbits[VV];
__device__ float g_msum[KK];
__device__ __align__(16) __nv_bfloat16 g_A2h[2*A2PART];  // [part][(b*27+off)][o][k]
__device__ __align__(16) __nv_bfloat16 g_modh[2*MODPART];// [part][b][o][k]
__device__ float g_Wk[BB*KK];
__device__ float g_dot[BB*MID], g_n1[BB*MID], g_n2[BB*MID];
__device__ float g_reg;

// ------------------------ init accumulators (every launch) --------------------
__global__ void k_init() {
    int t = threadIdx.x;
    if (t < BB*MID) { g_dot[t] = 0.f; g_n1[t] = 0.f; g_n2[t] = 0.f; }
    if (t < KK) g_msum[t] = 0.f;
    if (t == 0) g_reg = 0.f;
}

// ------------------------ mask bit-packing + fused msum -----------------------
__global__ void k_maskbits(const float* __restrict__ masks) {
    int v = blockIdx.x * 256 + threadIdx.x;
    unsigned w = 0;
#pragma unroll
    for (int k = 0; k < KK; k++)
        if (masks[k*VV + v] > 0.5f) w |= (1u << k);
    g_maskbits[v] = w;
    __shared__ int cnt[KK];
    if (threadIdx.x < KK) cnt[threadIdx.x] = 0;
    __syncthreads();
    int lane = threadIdx.x & 31;
#pragma unroll
    for (int k = 0; k < KK; k++) {
        unsigned ball = __ballot_sync(0xffffffffu, (w >> k) & 1u);
        if (lane == 0) atomicAdd(&cnt[k], __popc(ball));
    }
    __syncthreads();
    if (threadIdx.x < KK)
        atomicAdd(&g_msum[threadIdx.x], (float)cnt[threadIdx.x]);
}

// ------------------------ rf[b,k,c] -------------------------------------------
__global__ __launch_bounds__(256) void k_rf(const float* __restrict__ Z,
                                            float* __restrict__ out) {
    int b = blockIdx.x / CC, c = blockIdx.x % CC;
    const float* z = Z + (size_t)blockIdx.x * VV;
    float acc[KK];
#pragma unroll
    for (int k = 0; k < KK; k++) acc[k] = 0.f;
    for (int v = threadIdx.x*4; v < VV; v += 1024) {
        float4 zz = *(const float4*)&z[v];
        uint4 mb = *(const uint4*)&g_maskbits[v];
#pragma unroll
        for (int k = 0; k < KK; k++) {
            unsigned m = 1u << k;
            float t0 = ((mb.x & m) ? zz.x : 0.f) + ((mb.y & m) ? zz.y : 0.f);
            float t1 = ((mb.z & m) ? zz.z : 0.f) + ((mb.w & m) ? zz.w : 0.f);
            acc[k] += t0 + t1;
        }
    }
    __shared__ float sm[8*KK];
    int lane = threadIdx.x & 31, warp = threadIdx.x >> 5;
#pragma unroll
    for (int k = 0; k < KK; k++) {
        float v = acc[k];
#pragma unroll
        for (int o = 16; o; o >>= 1) v += __shfl_xor_sync(0xffffffffu, v, o);
        if (lane == k) sm[warp*KK + k] = v;
    }
    __syncthreads();
    if (threadIdx.x < KK) {
        int k = threadIdx.x;
        float t = 0.f;
#pragma unroll
        for (int w = 0; w < 8; w++) t += sm[w*KK + k];
        out[OUT_RF + (b*KK + k)*CC + c] = t / (g_msum[k] + 1e-6f);
    }
}

// ------------------------ MMD / reg / Wk / mod (tiny, 1 block) ----------------
__global__ __launch_bounds__(384) void k_stats(const float* __restrict__ outbuf,
        const int* __restrict__ labels, const float* __restrict__ ages,
        const float* __restrict__ pw,
        const float* __restrict__ mw1, const float* __restrict__ mb1,
        const float* __restrict__ mw2, const float* __restrict__ mb2) {
    __shared__ float x2_s[KK*BB];
    __shared__ float d2_s[KK*BB*BB];
    __shared__ float dk_s[4*KK];
    __shared__ float Dm_s[KK], nm_s[KK], base_s[KK], af_s[BB];
    __shared__ int   labi[BB];
    __shared__ float cnt[3];
    const float* rf = outbuf + OUT_RF;
    int t = threadIdx.x;

    if (t < BB) labi[t] = labels[t];
    if (t < 3)  cnt[t] = 0.f;
    __syncthreads();
    if (t == 0) for (int i = 0; i < BB; i++) cnt[labi[i]] += 1.f;

    if (t < BB*KK) {
        int b = t / KK, k = t % KK;
        const float* r = rf + (b*KK + k)*CC;
        float s = 0.f;
        for (int c = 0; c < CC; c++) s += r[c]*r[c];
        x2_s[k*BB + b] = s;
    }
    __syncthreads();
    for (int e = t; e < KK*BB*BB; e += 384) {
        int k = e / (BB*BB), r = e % (BB*BB), i = r / BB, j = r % BB;
        const float* ri = rf + (i*KK + k)*CC;
        const float* rj = rf + (j*KK + k)*CC;
        float s = 0.f;
        for (int c = 0; c < CC; c++) s += ri[c]*rj[c];
        d2_s[e] = fmaxf(x2_s[k*BB + i] + x2_s[k*BB + j] - 2.f*s, 0.f);
    }
    __syncthreads();
    if (t < 4*KK) {
        int si = t / KK, k = t % KK;
        const float sig[4] = {0.1f, 0.5f, 1.0f, 2.0f};
        float inv = 1.f / (2.f * sig[si]*sig[si]);
        float S[9]; float dd[3];
        for (int i = 0; i < 9; i++) S[i] = 0.f;
        dd[0] = dd[1] = dd[2] = 0.f;
        for (int i = 0; i < BB; i++) {
            int la = labi[i];
            for (int j = 0; j < BB; j++) {
                float kv = expf(-d2_s[k*BB*BB + i*BB + j] * inv);
                S[la*3 + labi[j]] += kv;
                if (i == j) dd[la] += kv;
            }
        }
        const int pa[3] = {2, 1, 2}, pb[3] = {0, 0, 1};
        float psum = 0.f;
        for (int p = 0; p < 3; p++) {
            float m = cnt[pa[p]], n = cnt[pb[p]];
            float t1 = (S[pa[p]*3 + pa[p]] - dd[pa[p]]) / (m*(m - 1.f));
            float t2 = (S[pb[p]*3 + pb[p]] - dd[pb[p]]) / (n*(n - 1.f));
            float t3 = S[pa[p]*3 + pb[p]] * (-2.f / (m*n));
            psum += t1 + t2 + t3;
        }
        dk_s[si*KK + k] = psum;
    }
    __syncthreads();
    if (t < KK)
        Dm_s[t] = 0.25f*(dk_s[t] + dk_s[KK + t] + dk_s[2*KK + t] + dk_s[3*KK + t]);
    __syncthreads();
    if (t == 0) {
        float mx = Dm_s[0];
        for (int k = 1; k < KK; k++) mx = fmaxf(mx, Dm_s[k]);
        mx = fmaxf(mx, 1e-6f);
        for (int k = 0; k < KK; k++) nm_s[k] = fmaxf(Dm_s[k]/mx, 0.f);
        float mp = -1e30f, mq = -1e30f;
        for (int k = 0; k < KK; k++) { mp = fmaxf(mp, pw[k]); mq = fmaxf(mq, nm_s[k]); }
        float sp = 0.f, sq = 0.f;
        for (int k = 0; k < KK; k++) { sp += expf(pw[k]-mp); sq += expf(nm_s[k]-mq); }
        float lsp = mp + logf(sp), lsq = mq + logf(sq);
        float reg = 0.f;
        for (int k = 0; k < KK; k++) {
            float lpk = pw[k] - lsp, lqk = nm_s[k] - lsq;
            float p = expf(lpk), q = expf(lqk);
            reg += 0.5f*q*(lqk - lpk) + 0.5f*p*(lpk - lqk);
        }
        g_reg = reg / (float)KK;
    }
    __syncthreads();
    if (t < KK) base_s[t] = 0.7f*pw[t] + 0.3f*nm_s[t];
    if (t < BB) {
        float x = 0.1f*(ages[t] - 50.f);
        af_s[t] = 1.f + fmaxf(x, 0.f) + log1pf(expf(-fabsf(x)));
    }
    __syncthreads();
    {
        int b = t >> 5, lane = t & 31;
        float v = fminf(fmaxf(base_s[lane]*af_s[b], 0.f), 2.f);
        float m = v;
#pragma unroll
        for (int o = 16; o; o >>= 1) m = fmaxf(m, __shfl_xor_sync(0xffffffffu, m, o));
        float e = expf(v - m);
        float s = e;
#pragma unroll
        for (int o = 16; o; o >>= 1) s += __shfl_xor_sync(0xffffffffu, s, o);
        g_Wk[b*KK + lane] = e / s;
    }
    {
        int b = t / KK, k = t % KK;
        float r[CC];
        const float* rr = rf + (b*KK + k)*CC;
        for (int c = 0; c < CC; c++) r[c] = rr[c];
        float h[RED];
#pragma unroll
        for (int q = 0; q < RED; q++) {
            float a = mb1[q];
            for (int c = 0; c < CC; c++) a += r[c]*mw1[q*CC + c];
            h[q] = fmaxf(a, 0.f);
        }
        for (int c = 0; c < CC; c++) {
            float a = mb2[c];
#pragma unroll
            for (int q = 0; q < RED; q++) a += h[q]*mw2[c*RED + q];
            float val = fmaxf(a, 0.f) + log1pf(expf(-fabsf(a)));
            __nv_bfloat16 hi = __float2bfloat16(val);
            __nv_bfloat16 lo = __float2bfloat16(val - __bfloat162float(hi));
            g_modh[(b*CC + c)*KK + k] = hi;
            g_modh[MODPART + (b*CC + c)*KK + k] = lo;
        }
    }
}

// ------------------------ A2[part,b,off,o,k] split-bf16 -----------------------
__global__ __launch_bounds__(256) void k_A2(const float* __restrict__ outbuf,
                                            const float* __restrict__ rw) {
    int m = blockIdx.x;                 // b*64 + o
    int b = m / CC, o = m % CC;
    __shared__ float rf_s[KK*CC];
    __shared__ float rw_s[CC*27];
    const float* rf = outbuf + OUT_RF + b*KK*CC;
    for (int i = threadIdx.x; i < KK*CC; i += 256) rf_s[i] = rf[i];
    for (int i = threadIdx.x; i < CC*27; i += 256) rw_s[i] = rw[o*CC*27 + i];
    __syncthreads();
    for (int t = threadIdx.x; t < 27*KK; t += 256) {
        int off = t / KK, k = t % KK;
        float a = 0.f;
        for (int c = 0; c < CC; c++) a += rf_s[k*CC + c] * rw_s[c*27 + off];
        __nv_bfloat16 hi = __float2bfloat16(a);
        __nv_bfloat16 lo = __float2bfloat16(a - __bfloat162float(hi));
        size_t idx = ((size_t)(b*27 + off)*CC + o)*KK + k;
        g_A2h[idx] = hi;
        g_A2h[A2PART + idx] = lo;
    }
}

// ------------------------ spatial[b,v] ----------------------------------------
__global__ __launch_bounds__(256) void k_spatial(float* __restrict__ out) {
    int b = blockIdx.y;
    int v = blockIdx.x*256 + threadIdx.x;
    __shared__ float wk[KK];
    if (threadIdx.x < KK) wk[threadIdx.x] = g_Wk[b*KK + threadIdx.x];
    __syncthreads();
    unsigned bits = g_maskbits[v];
    float s = 0.f;
#pragma unroll
    for (int k = 0; k < KK; k++) s += (bits & (1u << k)) ? wk[k] : 0.f;
    out[OUT_SP + b*VV + v] = s;
}

// ------------------------ fused zclean + conv-GEMM + epilogue -----------------
// phase1: cs = sw·Z, cn = nw·Z (per voxel), ortho stats, Zc = up_w·cs -> smem
// phase2: Zrec via mma.sync bf16 (split hi/lo); modf MMAs peeled (center mask)
// epilogue: out[b,o,v] = Zc[o,v] + 0.1 * Zrec * modf * spatial  (write-only)
#define MMA16816(C, A, B0, B1) \
  asm volatile("mma.sync.aligned.m16n8k16.row.col.f32.bf16.bf16.f32 " \
    "{%0,%1,%2,%3}, {%4,%5,%6,%7}, {%8,%9}, {%0,%1,%2,%3};" \
    : "+f"(C[0]), "+f"(C[1]), "+f"(C[2]), "+f"(C[3]) \
    : "r"(A[0]), "r"(A[1]), "r"(A[2]), "r"(A[3]), "r"(B0), "r"(B1))

// dynamic smem layout (bytes):
//   [0, 33792)        Zc  float[64][132]
//   [33792, 34304)    sp  float[128]
//   [34304, ...)      X region, reused:
//     phase1: sw f[2048] | nw f[2048] | uw f[2048]          (24576 B)
//     phase2: A bf16[2][2][64][40] (20480 B) | M bf16[2][64][40] (10240 B)
#define SM_BYTES 65024
#define A_IDX(buf,p,row,col) ((((buf)*2 + (p))*64 + (row))*40 + (col))
#define M_IDX(p,row,col)     (((p)*64 + (row))*40 + (col))

__global__ __launch_bounds__(256, 2) void k_conv(
        const float* __restrict__ Z,
        const float* __restrict__ sw, const float* __restrict__ nw,
        const float* __restrict__ uw, float* __restrict__ out) {
    extern __shared__ __align__(16) char smem_raw[];
    float* Zc   = (float*)smem_raw;                    // [64][132]
    float* sp_s = (float*)(smem_raw + 33792);          // [128]
    char*  X    = smem_raw + 34304;
    float* sw_s = (float*)X;
    float* nw_s = sw_s + 2048;
    float* uw_s = nw_s + 2048;
    __nv_bfloat16* A_s = (__nv_bfloat16*)X;
    __nv_bfloat16* M_s = (__nv_bfloat16*)(X + 20480);
    __shared__ float red[96];

    int b = blockIdx.y;
    int n0 = blockIdx.x * 128;
    int tid = threadIdx.x, lane = tid & 31, warp = tid >> 5;
    int d0 = n0 >> 10, h0 = (n0 >> 5) & 31;

    // ---------------- phase 1: zclean ----------------
    for (int i = tid; i < 2048; i += 256) {
        sw_s[i] = sw[i]; nw_s[i] = nw[i]; uw_s[i] = uw[i];
    }
    if (tid < 96) red[tid] = 0.f;
    if (tid < 128) sp_s[tid] = out[OUT_SP + b*VV + n0 + tid];
    __syncthreads();

    int v = tid & 127, half = tid >> 7;
    {
        float cs[16], cn[16];
#pragma unroll
        for (int o = 0; o < 16; o++) { cs[o] = 0.f; cn[o] = 0.f; }
        const float* zb = Z + (size_t)b*CC*VV + n0 + v;
        for (int c = 0; c < CC; c++) {
            float z = zb[(size_t)c*VV];
#pragma unroll
            for (int o = 0; o < 16; o++) {
                int oo = half*16 + o;
                cs[o] += sw_s[oo*CC + c]*z;
                cn[o] += nw_s[oo*CC + c]*z;
            }
        }
        // ortho stats: warp-reduce over 32 voxels, smem atomics
#pragma unroll
        for (int o = 0; o < 16; o++) {
            float d = cs[o]*cn[o], a = cs[o]*cs[o], e = cn[o]*cn[o];
#pragma unroll
            for (int s = 16; s; s >>= 1) {
                d += __shfl_xor_sync(0xffffffffu, d, s);
                a += __shfl_xor_sync(0xffffffffu, a, s);
                e += __shfl_xor_sync(0xffffffffu, e, s);
            }
            if (lane == 0) {
                int oo = half*16 + o;
                atomicAdd(&red[oo], d);
                atomicAdd(&red[32 + oo], a);
                atomicAdd(&red[64 + oo], e);
            }
        }
        // up-projection into Zc
        float zc[64];
#pragma unroll
        for (int j = 0; j < 64; j++) zc[j] = 0.f;
#pragma unroll
        for (int o = 0; o < 16; o++) {
            float co = cs[o];
#pragma unroll
            for (int j = 0; j < 64; j++)
                zc[j] += uw_s[j*MID + half*16 + o]*co;
        }
        if (half == 0) {
#pragma unroll
            for (int j = 0; j < 64; j++) Zc[j*132 + v] = zc[j];
        }
        __syncthreads();   // Zc half0 + red atomics complete; X region free
        if (half == 1) {
#pragma unroll
            for (int j = 0; j < 64; j++) Zc[j*132 + v] += zc[j];
        }
        if (tid < 96) {
            int o = tid & 31, which = tid >> 5;
            float val = red[tid];
            if (which == 0) atomicAdd(&g_dot[b*MID + o], val);
            else if (which == 1) atomicAdd(&g_n1[b*MID + o], val);
            else atomicAdd(&g_n2[b*MID + o], val);
        }
    }

    // ---------------- phase 2: conv GEMM ----------------
    {
        int row = tid >> 2, col = (tid & 3) * 8;
#pragma unroll
        for (int p = 0; p < 2; p++) {
            uint4 vm = ((const uint4*)(g_modh + (size_t)p*MODPART + b*2048))[tid];
            *(uint4*)&M_s[M_IDX(p,row,col)] = vm;
            uint4 va = ((const uint4*)(g_A2h + (size_t)p*A2PART + (size_t)(b*27 + 0)*2048))[tid];
            *(uint4*)&A_s[A_IDX(0,p,row,col)] = va;
        }
    }
    __syncthreads();   // also guards Zc half1 adds before epilogue reads

    int wm = (warp >> 2) * 32, wn = (warp & 3) * 32;
    float acc[2][4][4];
#pragma unroll
    for (int i = 0; i < 2; i++)
#pragma unroll
        for (int j = 0; j < 4; j++)
#pragma unroll
            for (int r = 0; r < 4; r++) acc[i][j][r] = 0.f;

    for (int off = 0; off < 27; off++) {
        int buf = off & 1;
        if (off < 26) {
            int row = tid >> 2, col = (tid & 3) * 8;
#pragma unroll
            for (int p = 0; p < 2; p++) {
                uint4 va = ((const uint4*)(g_A2h + (size_t)p*A2PART
                             + (size_t)(b*27 + off + 1)*2048))[tid];
                *(uint4*)&A_s[A_IDX(buf^1,p,row,col)] = va;
            }
        }
        int dz = off/9 - 1, dy = (off%9)/3 - 1, dx = off%3 - 1;
        int dd = d0 + dz, hh = h0 + (warp & 3) + dy, ww = lane + dx;
        unsigned word = 0;
        if (((unsigned)dd < 32u) && ((unsigned)hh < 32u) && ((unsigned)ww < 32u))
            word = g_maskbits[(dd << 10) + (hh << 5) + ww];

#pragma unroll
        for (int s = 0; s < 2; s++) {
            int kcol = 2*(lane & 3) + s*16;
            int r0 = wm + (lane >> 2);
            unsigned a[2][2][4];
#pragma unroll
            for (int p = 0; p < 2; p++)
#pragma unroll
            for (int i = 0; i < 2; i++) {
                a[p][i][0] = *(const unsigned*)&A_s[A_IDX(buf,p,r0 + i*16,kcol)];
                a[p][i][1] = *(const unsigned*)&A_s[A_IDX(buf,p,r0 + i*16 + 8,kcol)];
                a[p][i][2] = *(const unsigned*)&A_s[A_IDX(buf,p,r0 + i*16,kcol + 8)];
                a[p][i][3] = *(const unsigned*)&A_s[A_IDX(buf,p,r0 + i*16 + 8,kcol + 8)];
            }
#pragma unroll
            for (int j = 0; j < 4; j++) {
                unsigned wj = __shfl_sync(0xffffffffu, word, j*8 + (lane >> 2));
                unsigned t = wj >> (s*16 + 2*(lane & 3));
                unsigned b0 = (t & 1u ? 0x3F80u : 0u) | (t & 2u ? 0x3F800000u : 0u);
                unsigned t2 = t >> 8;
                unsigned b1 = (t2 & 1u ? 0x3F80u : 0u) | (t2 & 2u ? 0x3F800000u : 0u);
#pragma unroll
                for (int p = 0; p < 2; p++)
#pragma unroll
                for (int i = 0; i < 2; i++) MMA16816(acc[i][j], a[p][i], b0, b1);
            }
        }
        __syncthreads();
    }

    // peeled modfield MMAs at center offset (always in range)
    float macc[2][4][4];
#pragma unroll
    for (int i = 0; i < 2; i++)
#pragma unroll
        for (int j = 0; j < 4; j++)
#pragma unroll
            for (int r = 0; r < 4; r++) macc[i][j][r] = 0.f;
    {
        unsigned word = g_maskbits[(d0 << 10) + ((h0 + (warp & 3)) << 5) + lane];
#pragma unroll
        for (int s = 0; s < 2; s++) {
            int kcol = 2*(lane & 3) + s*16;
            int r0 = wm + (lane >> 2);
            unsigned am[2][2][4];
#pragma unroll
            for (int p = 0; p < 2; p++)
#pragma unroll
            for (int i = 0; i < 2; i++) {
                am[p][i][0] = *(const unsigned*)&M_s[M_IDX(p,r0 + i*16,kcol)];
                am[p][i][1] = *(const unsigned*)&M_s[M_IDX(p,r0 + i*16 + 8,kcol)];
                am[p][i][2] = *(const unsigned*)&M_s[M_IDX(p,r0 + i*16,kcol + 8)];
                am[p][i][3] = *(const unsigned*)&M_s[M_IDX(p,r0 + i*16 + 8,kcol + 8)];
            }
#pragma unroll
            for (int j = 0; j < 4; j++) {
                unsigned wj = __shfl_sync(0xffffffffu, word, j*8 + (lane >> 2));
                unsigned t = wj >> (s*16 + 2*(lane & 3));
                unsigned b0 = (t & 1u ? 0x3F80u : 0u) | (t & 2u ? 0x3F800000u : 0u);
                unsigned t2 = t >> 8;
                unsigned b1 = (t2 & 1u ? 0x3F80u : 0u) | (t2 & 2u ? 0x3F800000u : 0u);
#pragma unroll
                for (int p = 0; p < 2; p++)
#pragma unroll
                for (int i = 0; i < 2; i++) MMA16816(macc[i][j], am[p][i], b0, b1);
            }
        }
    }

    // epilogue: write-only  out = Zc + 0.1*Zrec*modf*sp
#pragma unroll
    for (int i = 0; i < 2; i++) {
#pragma unroll
        for (int j = 0; j < 4; j++) {
            int col = wn + j*8 + 2*(lane & 3);
            int r0 = wm + i*16 + (lane >> 2);
            float sp0 = 0.1f*sp_s[col], sp1 = 0.1f*sp_s[col+1];
            size_t base0 = (size_t)OUT_ZO + ((size_t)(b*CC + r0))*VV + n0 + col;
            float2 o0;
            o0.x = Zc[r0*132 + col]     + acc[i][j][0]*macc[i][j][0]*sp0;
            o0.y = Zc[r0*132 + col + 1] + acc[i][j][1]*macc[i][j][1]*sp1;
            *(float2*)(out + base0) = o0;
            size_t base1 = base0 + (size_t)8*VV;
            float2 o1;
            o1.x = Zc[(r0+8)*132 + col]     + acc[i][j][2]*macc[i][j][2]*sp0;
            o1.y = Zc[(r0+8)*132 + col + 1] + acc[i][j][3]*macc[i][j][3]*sp1;
            *(float2*)(out + base1) = o1;
        }
    }
}

// ------------------------ final scalar ----------------------------------------
__global__ void k_final(float* __restrict__ out) {
    int t = threadIdx.x;   // 384
    __shared__ float red[384];
    float n1 = sqrtf(g_n1[t]), n2 = sqrtf(g_n2[t]);
    float c = g_dot[t] / (fmaxf(n1, 1e-8f)*fmaxf(n2, 1e-8f));
    red[t] = fabsf(c);
    __syncthreads();
    if (t == 0) {
        float s = 0.f;
        for (int i = 0; i < 384; i++) s += red[i];
        out[OUT_LOSS] = g_reg + s/384.f;
    }
}

// ------------------------ launch ----------------------------------------------
extern "C" void kernel_launch(void* const* d_in, const int* in_sizes, int n_in,
                              void* d_out, int out_size) {
    const float* Z      = (const float*)d_in[0];
    const float* masks  = (const float*)d_in[1];
    const int*   labels = (const int*)  d_in[2];
    const float* ages   = (const float*)d_in[3];
    const float* pw     = (const float*)d_in[4];
    const float* sw     = (const float*)d_in[5];
    const float* nw     = (const float*)d_in[6];
    const float* uw     = (const float*)d_in[7];
    const float* rw     = (const float*)d_in[8];
    const float* mw1    = (const float*)d_in[9];
    const float* mb1    = (const float*)d_in[10];
    const float* mw2    = (const float*)d_in[11];
    const float* mb2    = (const float*)d_in[12];
    float* out = (float*)d_out;

    cudaFuncSetAttribute(k_conv, cudaFuncAttributeMaxDynamicSharedMemorySize,
                         SM_BYTES);

    k_init<<<1, 384>>>();
    k_maskbits<<<VV/256, 256>>>(masks);
    k_rf<<<BB*CC, 256>>>(Z, out);
    k_stats<<<1, 384>>>(out, labels, ages, pw, mw1, mb1, mw2, mb2);
    k_A2<<<BB*CC, 256>>>(out, rw);
    dim3 gs(VV/256, BB);
    k_spatial<<<gs, 256>>>(out);
    dim3 gc(VV/128, BB);
    k_conv<<<gc, 256, SM_BYTES>>>(Z, sw, nw, uw, out);
    k_final<<<1, 384>>>(out);
}

// round 16
// speedup vs baseline: 2.4945x; 1.1780x over previous
#include <cuda_runtime.h>
#include <cuda_bf16.h>
#include <math.h>

#define BB 12
#define CC 64
#define KK 32
#define VV 32768
#define MID 32
#define RED 16

#define OUT_RF 0
#define OUT_SP (BB*KK*CC)                 /* 24576  */
#define OUT_ZO (OUT_SP + BB*VV)           /* 417792 */
#define OUT_LOSS (OUT_ZO + BB*CC*VV)      /* 25583616 */

#define A2PART (BB*27*CC*KK)              /* 663552  */
#define MODPART (BB*CC*KK)                /* 24576   */

// ------------------------ device scratch (static, no allocs) ------------------
__device__ __align__(16) unsigned g_maskbits[VV];
__device__ float g_msum[KK];
__device__ __align__(16) __nv_bfloat16 g_A2h[2*A2PART];  // [part][(b*27+off)][o][k]
__device__ __align__(16) __nv_bfloat16 g_modh[2*MODPART];// [part][b][o][k]
__device__ float g_Wk[BB*KK];
__device__ float g_dot[BB*MID], g_n1[BB*MID], g_n2[BB*MID];
__device__ float g_reg;

// ------------------------ init accumulators (every launch) --------------------
__global__ void k_init() {
    int t = threadIdx.x;
    if (t < BB*MID) { g_dot[t] = 0.f; g_n1[t] = 0.f; g_n2[t] = 0.f; }
    if (t < KK) g_msum[t] = 0.f;
    if (t == 0) g_reg = 0.f;
}

// ------------------------ mask bit-packing + fused msum -----------------------
__global__ void k_maskbits(const float* __restrict__ masks) {
    int v = blockIdx.x * 256 + threadIdx.x;
    unsigned w = 0;
#pragma unroll
    for (int k = 0; k < KK; k++)
        if (masks[k*VV + v] > 0.5f) w |= (1u << k);
    g_maskbits[v] = w;
    __shared__ int cnt[KK];
    if (threadIdx.x < KK) cnt[threadIdx.x] = 0;
    __syncthreads();
    int lane = threadIdx.x & 31;
#pragma unroll
    for (int k = 0; k < KK; k++) {
        unsigned ball = __ballot_sync(0xffffffffu, (w >> k) & 1u);
        if (lane == 0) atomicAdd(&cnt[k], __popc(ball));
    }
    __syncthreads();
    if (threadIdx.x < KK)
        atomicAdd(&g_msum[threadIdx.x], (float)cnt[threadIdx.x]);
}

// ------------------------ rf[b,k,c] -------------------------------------------
__global__ __launch_bounds__(256) void k_rf(const float* __restrict__ Z,
                                            float* __restrict__ out) {
    int b = blockIdx.x / CC, c = blockIdx.x % CC;
    const float* z = Z + (size_t)blockIdx.x * VV;
    float acc[KK];
#pragma unroll
    for (int k = 0; k < KK; k++) acc[k] = 0.f;
    for (int v = threadIdx.x*4; v < VV; v += 1024) {
        float4 zz = *(const float4*)&z[v];
        uint4 mb = *(const uint4*)&g_maskbits[v];
#pragma unroll
        for (int k = 0; k < KK; k++) {
            unsigned m = 1u << k;
            if (mb.x & m) acc[k] += zz.x;
            if (mb.y & m) acc[k] += zz.y;
            if (mb.z & m) acc[k] += zz.z;
            if (mb.w & m) acc[k] += zz.w;
        }
    }
    __shared__ float sm[8*KK];
    int lane = threadIdx.x & 31, warp = threadIdx.x >> 5;
#pragma unroll
    for (int k = 0; k < KK; k++) {
        float v = acc[k];
#pragma unroll
        for (int o = 16; o; o >>= 1) v += __shfl_xor_sync(0xffffffffu, v, o);
        if (lane == k) sm[warp*KK + k] = v;
    }
    __syncthreads();
    if (threadIdx.x < KK) {
        int k = threadIdx.x;
        float t = 0.f;
#pragma unroll
        for (int w = 0; w < 8; w++) t += sm[w*KK + k];
        out[OUT_RF + (b*KK + k)*CC + c] = t / (g_msum[k] + 1e-6f);
    }
}

// ------------------------ MMD / reg / Wk (1 block, rf in smem) ----------------
__global__ __launch_bounds__(384) void k_mmd(const float* __restrict__ outbuf,
        const int* __restrict__ labels, const float* __restrict__ ages,
        const float* __restrict__ pw) {
    extern __shared__ __align__(16) float rf_s[];       // [BB*KK*CC] = 96 KB
    __shared__ float x2_s[KK*BB];
    __shared__ float d2_s[KK*BB*BB];
    __shared__ float dk_s[4*KK];
    __shared__ float Dm_s[KK], nm_s[KK], base_s[KK], af_s[BB];
    __shared__ int   labi[BB];
    __shared__ float cnt[3];
    int t = threadIdx.x;

    for (int i = t*4; i < BB*KK*CC; i += 384*4)
        *(float4*)&rf_s[i] = *(const float4*)&outbuf[OUT_RF + i];
    if (t < BB) labi[t] = labels[t];
    if (t < 3)  cnt[t] = 0.f;
    __syncthreads();
    if (t == 0) for (int i = 0; i < BB; i++) cnt[labi[i]] += 1.f;

    // x2[b,k]: thread t = b*KK + k (384 exactly)
    {
        int b = t / KK, k = t % KK;
        const float* r = rf_s + (b*KK + k)*CC;
        float s = 0.f;
#pragma unroll
        for (int c = 0; c < CC; c++) s += r[c]*r[c];
        x2_s[k*BB + b] = s;
    }
    __syncthreads();
    for (int e = t; e < KK*BB*BB; e += 384) {
        int k = e / (BB*BB), r = e % (BB*BB), i = r / BB, j = r % BB;
        const float* ri = rf_s + (i*KK + k)*CC;
        const float* rj = rf_s + (j*KK + k)*CC;
        float s = 0.f;
#pragma unroll
        for (int c = 0; c < CC; c++) s += ri[c]*rj[c];
        d2_s[e] = fmaxf(x2_s[k*BB + i] + x2_s[k*BB + j] - 2.f*s, 0.f);
    }
    __syncthreads();
    if (t < 4*KK) {
        int si = t / KK, k = t % KK;
        const float sig[4] = {0.1f, 0.5f, 1.0f, 2.0f};
        float inv = 1.f / (2.f * sig[si]*sig[si]);
        float S[9]; float dd[3];
        for (int i = 0; i < 9; i++) S[i] = 0.f;
        dd[0] = dd[1] = dd[2] = 0.f;
        for (int i = 0; i < BB; i++) {
            int la = labi[i];
#pragma unroll
            for (int j = 0; j < BB; j++) {
                float kv = __expf(-d2_s[k*BB*BB + i*BB + j] * inv);
                // __expf max rel err ~2^-21 on kernel values in (0,1]; MMD uses
                // differences of O(1) sums -> error ~1e-6, well under 1e-3.
                S[la*3 + labi[j]] += kv;
                if (i == j) dd[la] += kv;
            }
        }
        const int pa[3] = {2, 1, 2}, pb[3] = {0, 0, 1};
        float psum = 0.f;
        for (int p = 0; p < 3; p++) {
            float m = cnt[pa[p]], n = cnt[pb[p]];
            float t1 = (S[pa[p]*3 + pa[p]] - dd[pa[p]]) / (m*(m - 1.f));
            float t2 = (S[pb[p]*3 + pb[p]] - dd[pb[p]]) / (n*(n - 1.f));
            float t3 = S[pa[p]*3 + pb[p]] * (-2.f / (m*n));
            psum += t1 + t2 + t3;
        }
        dk_s[si*KK + k] = psum;
    }
    __syncthreads();
    if (t < KK)
        Dm_s[t] = 0.25f*(dk_s[t] + dk_s[KK + t] + dk_s[2*KK + t] + dk_s[3*KK + t]);
    __syncthreads();
    if (t == 0) {
        float mx = Dm_s[0];
        for (int k = 1; k < KK; k++) mx = fmaxf(mx, Dm_s[k]);
        mx = fmaxf(mx, 1e-6f);
        for (int k = 0; k < KK; k++) nm_s[k] = fmaxf(Dm_s[k]/mx, 0.f);
        float mp = -1e30f, mq = -1e30f;
        for (int k = 0; k < KK; k++) { mp = fmaxf(mp, pw[k]); mq = fmaxf(mq, nm_s[k]); }
        float sp = 0.f, sq = 0.f;
        for (int k = 0; k < KK; k++) { sp += expf(pw[k]-mp); sq += expf(nm_s[k]-mq); }
        float lsp = mp + logf(sp), lsq = mq + logf(sq);
        float reg = 0.f;
        for (int k = 0; k < KK; k++) {
            float lpk = pw[k] - lsp, lqk = nm_s[k] - lsq;
            float p = expf(lpk), q = expf(lqk);
            reg += 0.5f*q*(lqk - lpk) + 0.5f*p*(lpk - lqk);
        }
        g_reg = reg / (float)KK;
    }
    __syncthreads();
    if (t < KK) base_s[t] = 0.7f*pw[t] + 0.3f*nm_s[t];
    if (t < BB) {
        float x = 0.1f*(ages[t] - 50.f);
        af_s[t] = 1.f + fmaxf(x, 0.f) + log1pf(expf(-fabsf(x)));
    }
    __syncthreads();
    {
        int b = t >> 5, lane = t & 31;
        float v = fminf(fmaxf(base_s[lane]*af_s[b], 0.f), 2.f);
        float m = v;
#pragma unroll
        for (int o = 16; o; o >>= 1) m = fmaxf(m, __shfl_xor_sync(0xffffffffu, m, o));
        float e = expf(v - m);
        float s = e;
#pragma unroll
        for (int o = 16; o; o >>= 1) s += __shfl_xor_sync(0xffffffffu, s, o);
        g_Wk[b*KK + lane] = e / s;
    }
}

// ------------------------ mod MLP (12 blocks, smem-staged) --------------------
__global__ __launch_bounds__(512) void k_mod(const float* __restrict__ outbuf,
        const float* __restrict__ mw1, const float* __restrict__ mb1,
        const float* __restrict__ mw2, const float* __restrict__ mb2) {
    int b = blockIdx.x;
    int t = threadIdx.x;
    __shared__ float rf_s[KK*CC];        // 8 KB
    __shared__ float w1_s[RED*CC];       // 4 KB
    __shared__ float w2_s[CC*RED];       // 4 KB
    __shared__ float b1_s[RED], b2_s[CC];
    __shared__ float h_s[KK*RED];        // 2 KB

    for (int i = t; i < KK*CC; i += 512) rf_s[i] = outbuf[OUT_RF + b*KK*CC + i];
    for (int i = t; i < RED*CC; i += 512) w1_s[i] = mw1[i];
    for (int i = t; i < CC*RED; i += 512) w2_s[i] = mw2[i];
    if (t < RED) b1_s[t] = mb1[t];
    if (t < CC)  b2_s[t] = mb2[t];
    __syncthreads();

    // stage 1: h[k][q], thread = k*RED + q (512 exactly)
    {
        int k = t >> 4, q = t & 15;
        float a = b1_s[q];
#pragma unroll
        for (int c = 0; c < CC; c++) a += rf_s[k*CC + c]*w1_s[q*CC + c];
        h_s[k*RED + q] = fmaxf(a, 0.f);
    }
    __syncthreads();

    // stage 2: mod[k][c], 2048 entries / 512 threads
    for (int e = t; e < KK*CC; e += 512) {
        int k = e >> 6, c = e & 63;
        float a = b2_s[c];
#pragma unroll
        for (int q = 0; q < RED; q++) a += h_s[k*RED + q]*w2_s[c*RED + q];
        float val = fmaxf(a, 0.f) + log1pf(expf(-fabsf(a)));
        __nv_bfloat16 hi = __float2bfloat16(val);
        __nv_bfloat16 lo = __float2bfloat16(val - __bfloat162float(hi));
        g_modh[(b*CC + c)*KK + k] = hi;
        g_modh[MODPART + (b*CC + c)*KK + k] = lo;
    }
}

// ------------------------ A2[part,b,off,o,k] split-bf16 -----------------------
__global__ __launch_bounds__(256) void k_A2(const float* __restrict__ outbuf,
                                            const float* __restrict__ rw) {
    int m = blockIdx.x;                 // b*64 + o
    int b = m / CC, o = m % CC;
    __shared__ float rf_s[KK*CC];
    __shared__ float rw_s[CC*27];
    const float* rf = outbuf + OUT_RF + b*KK*CC;
    for (int i = threadIdx.x; i < KK*CC; i += 256) rf_s[i] = rf[i];
    for (int i = threadIdx.x; i < CC*27; i += 256) rw_s[i] = rw[o*CC*27 + i];
    __syncthreads();
    for (int t = threadIdx.x; t < 27*KK; t += 256) {
        int off = t / KK, k = t % KK;
        float a = 0.f;
#pragma unroll
        for (int c = 0; c < CC; c++) a += rf_s[k*CC + c] * rw_s[c*27 + off];
        __nv_bfloat16 hi = __float2bfloat16(a);
        __nv_bfloat16 lo = __float2bfloat16(a - __bfloat162float(hi));
        size_t idx = ((size_t)(b*27 + off)*CC + o)*KK + k;
        g_A2h[idx] = hi;
        g_A2h[A2PART + idx] = lo;
    }
}

// ------------------------ fused zclean + spatial + conv-GEMM ------------------
#define MMA16816(C, A, B0, B1) \
  asm volatile("mma.sync.aligned.m16n8k16.row.col.f32.bf16.bf16.f32 " \
    "{%0,%1,%2,%3}, {%4,%5,%6,%7}, {%8,%9}, {%0,%1,%2,%3};" \
    : "+f"(C[0]), "+f"(C[1]), "+f"(C[2]), "+f"(C[3]) \
    : "r"(A[0]), "r"(A[1]), "r"(A[2]), "r"(A[3]), "r"(B0), "r"(B1))

// dynamic smem layout (bytes):
//   [0, 33792)        Zc  float[64][132]
//   [33792, 34304)    sp  float[128]
//   [34304, ...)      X region, reused:
//     phase1: sw f[2048] | nw f[2048] | uw f[2048]          (24576 B)
//     phase2: A bf16[2][2][64][40] (20480 B) | M bf16[2][64][40] (10240 B)
#define SM_BYTES 65024
#define A_IDX(buf,p,row,col) ((((buf)*2 + (p))*64 + (row))*40 + (col))
#define M_IDX(p,row,col)     (((p)*64 + (row))*40 + (col))

__global__ __launch_bounds__(256, 2) void k_conv(
        const float* __restrict__ Z,
        const float* __restrict__ sw, const float* __restrict__ nw,
        const float* __restrict__ uw, float* __restrict__ out) {
    extern __shared__ __align__(16) char smem_raw[];
    float* Zc   = (float*)smem_raw;                    // [64][132]
    float* sp_s = (float*)(smem_raw + 33792);          // [128]
    char*  X    = smem_raw + 34304;
    float* sw_s = (float*)X;
    float* nw_s = sw_s + 2048;
    float* uw_s = nw_s + 2048;
    __nv_bfloat16* A_s = (__nv_bfloat16*)X;
    __nv_bfloat16* M_s = (__nv_bfloat16*)(X + 20480);
    __shared__ float red[96];
    __shared__ float wk_s[KK];

    int b = blockIdx.y;
    int n0 = blockIdx.x * 128;
    int tid = threadIdx.x, lane = tid & 31, warp = tid >> 5;
    int d0 = n0 >> 10, h0 = (n0 >> 5) & 31;

    // ---------------- phase 1: zclean + spatial ----------------
    for (int i = tid; i < 2048; i += 256) {
        sw_s[i] = sw[i]; nw_s[i] = nw[i]; uw_s[i] = uw[i];
    }
    if (tid < 96) red[tid] = 0.f;
    if (tid < KK) wk_s[tid] = g_Wk[b*KK + tid];
    __syncthreads();

    if (tid < 128) {
        unsigned bits = g_maskbits[n0 + tid];
        float s = 0.f;
#pragma unroll
        for (int k = 0; k < KK; k++)
            if ((bits >> k) & 1u) s += wk_s[k];
        sp_s[tid] = s;
        out[OUT_SP + b*VV + n0 + tid] = s;
    }

    int v = tid & 127, half = tid >> 7;
    {
        float cs[16], cn[16];
#pragma unroll
        for (int o = 0; o < 16; o++) { cs[o] = 0.f; cn[o] = 0.f; }
        const float* zb = Z + (size_t)b*CC*VV + n0 + v;
        for (int c = 0; c < CC; c++) {
            float z = zb[(size_t)c*VV];
#pragma unroll
            for (int o = 0; o < 16; o++) {
                int oo = half*16 + o;
                cs[o] += sw_s[oo*CC + c]*z;
                cn[o] += nw_s[oo*CC + c]*z;
            }
        }
#pragma unroll
        for (int o = 0; o < 16; o++) {
            float d = cs[o]*cn[o], a = cs[o]*cs[o], e = cn[o]*cn[o];
#pragma unroll
            for (int s = 16; s; s >>= 1) {
                d += __shfl_xor_sync(0xffffffffu, d, s);
                a += __shfl_xor_sync(0xffffffffu, a, s);
                e += __shfl_xor_sync(0xffffffffu, e, s);
            }
            if (lane == 0) {
                int oo = half*16 + o;
                atomicAdd(&red[oo], d);
                atomicAdd(&red[32 + oo], a);
                atomicAdd(&red[64 + oo], e);
            }
        }
        float zc[64];
#pragma unroll
        for (int j = 0; j < 64; j++) zc[j] = 0.f;
#pragma unroll
        for (int o = 0; o < 16; o++) {
            float co = cs[o];
#pragma unroll
            for (int j = 0; j < 64; j++)
                zc[j] += uw_s[j*MID + half*16 + o]*co;
        }
        if (half == 0) {
#pragma unroll
            for (int j = 0; j < 64; j++) Zc[j*132 + v] = zc[j];
        }
        __syncthreads();   // Zc half0 + red atomics complete; X region free
        if (half == 1) {
#pragma unroll
            for (int j = 0; j < 64; j++) Zc[j*132 + v] += zc[j];
        }
        if (tid < 96) {
            int o = tid & 31, which = tid >> 5;
            float val = red[tid];
            if (which == 0) atomicAdd(&g_dot[b*MID + o], val);
            else if (which == 1) atomicAdd(&g_n1[b*MID + o], val);
            else atomicAdd(&g_n2[b*MID + o], val);
        }
    }

    // ---------------- phase 2: conv GEMM ----------------
    {
        int row = tid >> 2, col = (tid & 3) * 8;
#pragma unroll
        for (int p = 0; p < 2; p++) {
            uint4 vm = ((const uint4*)(g_modh + (size_t)p*MODPART + b*2048))[tid];
            *(uint4*)&M_s[M_IDX(p,row,col)] = vm;
            uint4 va = ((const uint4*)(g_A2h + (size_t)p*A2PART + (size_t)(b*27 + 0)*2048))[tid];
            *(uint4*)&A_s[A_IDX(0,p,row,col)] = va;
        }
    }
    __syncthreads();   // also guards Zc half1 adds before epilogue reads

    int wm = (warp >> 2) * 32, wn = (warp & 3) * 32;
    float acc[2][4][4];
#pragma unroll
    for (int i = 0; i < 2; i++)
#pragma unroll
        for (int j = 0; j < 4; j++)
#pragma unroll
            for (int r = 0; r < 4; r++) acc[i][j][r] = 0.f;

    for (int off = 0; off < 27; off++) {
        int buf = off & 1;
        if (off < 26) {
            int row = tid >> 2, col = (tid & 3) * 8;
#pragma unroll
            for (int p = 0; p < 2; p++) {
                uint4 va = ((const uint4*)(g_A2h + (size_t)p*A2PART
                             + (size_t)(b*27 + off + 1)*2048))[tid];
                *(uint4*)&A_s[A_IDX(buf^1,p,row,col)] = va;
            }
        }
        int dz = off/9 - 1, dy = (off%9)/3 - 1, dx = off%3 - 1;
        int dd = d0 + dz, hh = h0 + (warp & 3) + dy, ww = lane + dx;
        unsigned word = 0;
        if (((unsigned)dd < 32u) && ((unsigned)hh < 32u) && ((unsigned)ww < 32u))
            word = g_maskbits[(dd << 10) + (hh << 5) + ww];

#pragma unroll
        for (int s = 0; s < 2; s++) {
            int kcol = 2*(lane & 3) + s*16;
            int r0 = wm + (lane >> 2);
            unsigned a[2][2][4];
#pragma unroll
            for (int p = 0; p < 2; p++)
#pragma unroll
            for (int i = 0; i < 2; i++) {
                a[p][i][0] = *(const unsigned*)&A_s[A_IDX(buf,p,r0 + i*16,kcol)];
                a[p][i][1] = *(const unsigned*)&A_s[A_IDX(buf,p,r0 + i*16 + 8,kcol)];
                a[p][i][2] = *(const unsigned*)&A_s[A_IDX(buf,p,r0 + i*16,kcol + 8)];
                a[p][i][3] = *(const unsigned*)&A_s[A_IDX(buf,p,r0 + i*16 + 8,kcol + 8)];
            }
#pragma unroll
            for (int j = 0; j < 4; j++) {
                unsigned wj = __shfl_sync(0xffffffffu, word, j*8 + (lane >> 2));
                unsigned t = wj >> (s*16 + 2*(lane & 3));
                unsigned b0 = (t & 1u ? 0x3F80u : 0u) | (t & 2u ? 0x3F800000u : 0u);
                unsigned t2 = t >> 8;
                unsigned b1 = (t2 & 1u ? 0x3F80u : 0u) | (t2 & 2u ? 0x3F800000u : 0u);
#pragma unroll
                for (int p = 0; p < 2; p++)
#pragma unroll
                for (int i = 0; i < 2; i++) MMA16816(acc[i][j], a[p][i], b0, b1);
            }
        }
        __syncthreads();
    }

    // peeled modfield MMAs at center offset (always in range)
    float macc[2][4][4];
#pragma unroll
    for (int i = 0; i < 2; i++)
#pragma unroll
        for (int j = 0; j < 4; j++)
#pragma unroll
            for (int r = 0; r < 4; r++) macc[i][j][r] = 0.f;
    {
        unsigned word = g_maskbits[(d0 << 10) + ((h0 + (warp & 3)) << 5) + lane];
#pragma unroll
        for (int s = 0; s < 2; s++) {
            int kcol = 2*(lane & 3) + s*16;
            int r0 = wm + (lane >> 2);
            unsigned am[2][2][4];
#pragma unroll
            for (int p = 0; p < 2; p++)
#pragma unroll
            for (int i = 0; i < 2; i++) {
                am[p][i][0] = *(const unsigned*)&M_s[M_IDX(p,r0 + i*16,kcol)];
                am[p][i][1] = *(const unsigned*)&M_s[M_IDX(p,r0 + i*16 + 8,kcol)];
                am[p][i][2] = *(const unsigned*)&M_s[M_IDX(p,r0 + i*16,kcol + 8)];
                am[p][i][3] = *(const unsigned*)&M_s[M_IDX(p,r0 + i*16 + 8,kcol + 8)];
            }
#pragma unroll
            for (int j = 0; j < 4; j++) {
                unsigned wj = __shfl_sync(0xffffffffu, word, j*8 + (lane >> 2));
                unsigned t = wj >> (s*16 + 2*(lane & 3));
                unsigned b0 = (t & 1u ? 0x3F80u : 0u) | (t & 2u ? 0x3F800000u : 0u);
                unsigned t2 = t >> 8;
                unsigned b1 = (t2 & 1u ? 0x3F80u : 0u) | (t2 & 2u ? 0x3F800000u : 0u);
#pragma unroll
                for (int p = 0; p < 2; p++)
#pragma unroll
                for (int i = 0; i < 2; i++) MMA16816(macc[i][j], am[p][i], b0, b1);
            }
        }
    }

    // epilogue: write-only  out = Zc + 0.1*Zrec*modf*sp
#pragma unroll
    for (int i = 0; i < 2; i++) {
#pragma unroll
        for (int j = 0; j < 4; j++) {
            int col = wn + j*8 + 2*(lane & 3);
            int r0 = wm + i*16 + (lane >> 2);
            float sp0 = 0.1f*sp_s[col], sp1 = 0.1f*sp_s[col+1];
            size_t base0 = (size_t)OUT_ZO + ((size_t)(b*CC + r0))*VV + n0 + col;
            float2 o0;
            o0.x = Zc[r0*132 + col]     + acc[i][j][0]*macc[i][j][0]*sp0;
            o0.y = Zc[r0*132 + col + 1] + acc[i][j][1]*macc[i][j][1]*sp1;
            *(float2*)(out + base0) = o0;
            size_t base1 = base0 + (size_t)8*VV;
            float2 o1;
            o1.x = Zc[(r0+8)*132 + col]     + acc[i][j][2]*macc[i][j][2]*sp0;
            o1.y = Zc[(r0+8)*132 + col + 1] + acc[i][j][3]*macc[i][j][3]*sp1;
            *(float2*)(out + base1) = o1;
        }
    }
}

// ------------------------ final scalar ----------------------------------------
__global__ void k_final(float* __restrict__ out) {
    int t = threadIdx.x;   // 384
    __shared__ float red[384];
    float n1 = sqrtf(g_n1[t]), n2 = sqrtf(g_n2[t]);
    float c = g_dot[t] / (fmaxf(n1, 1e-8f)*fmaxf(n2, 1e-8f));
    red[t] = fabsf(c);
    __syncthreads();
    if (t == 0) {
        float s = 0.f;
        for (int i = 0; i < 384; i++) s += red[i];
        out[OUT_LOSS] = g_reg + s/384.f;
    }
}

// ------------------------ launch ----------------------------------------------
extern "C" void kernel_launch(void* const* d_in, const int* in_sizes, int n_in,
                              void* d_out, int out_size) {
    const float* Z      = (const float*)d_in[0];
    const float* masks  = (const float*)d_in[1];
    const int*   labels = (const int*)  d_in[2];
    const float* ages   = (const float*)d_in[3];
    const float* pw     = (const float*)d_in[4];
    const float* sw     = (const float*)d_in[5];
    const float* nw     = (const float*)d_in[6];
    const float* uw     = (const float*)d_in[7];
    const float* rw     = (const float*)d_in[8];
    const float* mw1    = (const float*)d_in[9];
    const float* mb1    = (const float*)d_in[10];
    const float* mw2    = (const float*)d_in[11];
    const float* mb2    = (const float*)d_in[12];
    float* out = (float*)d_out;

    cudaFuncSetAttribute(k_conv, cudaFuncAttributeMaxDynamicSharedMemorySize,
                         SM_BYTES);
    cudaFuncSetAttribute(k_mmd, cudaFuncAttributeMaxDynamicSharedMemorySize,
                         BB*KK*CC*4);

    k_init<<<1, 384>>>();
    k_maskbits<<<VV/256, 256>>>(masks);
    k_rf<<<BB*CC, 256>>>(Z, out);
    k_mod<<<BB, 512>>>(out, mw1, mb1, mw2, mb2);
    k_A2<<<BB*CC, 256>>>(out, rw);
    k_mmd<<<1, 384, BB*KK*CC*4>>>(out, labels, ages, pw);
    dim3 gc(VV/128, BB);
    k_conv<<<gc, 256, SM_BYTES>>>(Z, sw, nw, uw, out);
    k_final<<<1, 384>>>(out);
}